// round 6
// baseline (speedup 1.0000x reference)
#include <cuda_runtime.h>
#include <math_constants.h>

#define BB 4
#define SS 4096
#define DD 1024
#define WND 128
#define KTOP 64
#define RSTRIDE 10
#define RBUDGET 409

#define NSC 2048                    /* scores blocks (8 rows each)      */
#define NJA (BB * SS)               /* regionA rows (window+zeros)      */
#define NJB (BB * (SS - WND))       /* regionB rows (prefix, i>=WND)    */
#define GRID_TOTAL (NSC + BB + NJA + NJB)

// scratch (no allocation allowed)
__device__ unsigned g_keys[BB * SS];
__device__ unsigned char g_flag[BB * SS];
__device__ float g_prefval[BB * SS];
__device__ float g_fvalid[BB * SS];
__device__ unsigned g_scoresDone;
__device__ unsigned g_ready[BB];

// ---------------------------------------------------------------------------
__global__ void init_kernel() {
    if (threadIdx.x == 0) g_scoresDone = 0u;
    if (threadIdx.x < BB) g_ready[threadIdx.x] = 0u;
}

// ---------------------------------------------------------------------------
__global__ void __launch_bounds__(256)
fused_kernel(const float* __restrict__ h, const int* __restrict__ am,
             const float* __restrict__ w, float* __restrict__ out,
             long long out_size) {
    __shared__ unsigned hist[4096];   // topk path only: hist -> cand -> prefix
    __shared__ unsigned s_w[8];
    __shared__ unsigned s_w2[8];
    __shared__ int s_T;
    __shared__ unsigned s_above, s_ncand;

    int bid = blockIdx.x;
    int t = threadIdx.x;
    int lane = t & 31, wid = t >> 5;

    // ===================== role 1: scores (bids [0,NSC)) ====================
    if (bid < NSC) {
        int r = bid * 8 + wid;        // one row per warp
        const float4* hv = reinterpret_cast<const float4*>(h + (size_t)r * DD);
        const float4* wv = reinterpret_cast<const float4*>(w);
        float4 a[8];
#pragma unroll
        for (int u = 0; u < 8; u++) a[u] = __ldcs(&hv[lane + u * 32]);
        float acc0 = 0.f, acc1 = 0.f;
#pragma unroll
        for (int u = 0; u < 8; u++) {
            float4 bw = wv[lane + u * 32];
            acc0 += a[u].x * bw.x + a[u].y * bw.y;
            acc1 += a[u].z * bw.z + a[u].w * bw.w;
        }
        float acc = acc0 + acc1;
#pragma unroll
        for (int o = 16; o; o >>= 1) acc += __shfl_xor_sync(0xffffffffu, acc, o);
        if (lane == 0) {
            int amv = am[r];
            float vv = amv ? acc : -CUDART_INF_F;
            unsigned k = __float_as_uint(vv);
            k = (k & 0x80000000u) ? ~k : (k | 0x80000000u);
            g_keys[r] = k;
            int s = r & (SS - 1);
            g_flag[r] = ((s % RSTRIDE) == 0 && (s / RSTRIDE) < RBUDGET) ? 1 : 0;
        }
        __syncthreads();
        if (t == 0) {
            __threadfence();
            atomicAdd(&g_scoresDone, 1u);
        }
        return;
    }

    // ===================== role 2: topk (bids [NSC,NSC+BB)) =================
    if (bid < NSC + BB) {
        int b = bid - NSC;
        if (t == 0) {
            while (*(volatile unsigned*)&g_scoresDone < (unsigned)NSC)
                __nanosleep(64);
            __threadfence();
        }
        __syncthreads();

        // histogram of top-12 key bits
#pragma unroll
        for (int c = 0; c < 16; c++) hist[t + 256 * c] = 0;
        if (t == 0) s_ncand = 0;
        __syncthreads();
#pragma unroll
        for (int c = 0; c < 16; c++) {
            unsigned k = __ldcg(&g_keys[b * SS + t + 256 * c]);
            atomicAdd(&hist[k >> 20], 1u);
        }
        __syncthreads();

        // suffix scan: count of keys in bins strictly above each bin
        unsigned sl = 0;
#pragma unroll
        for (int x = 0; x < 16; x++) sl += hist[t * 16 + x];
        unsigned v = sl;
#pragma unroll
        for (int o = 1; o < 32; o <<= 1) {
            unsigned u = __shfl_down_sync(0xffffffffu, v, o);
            if (lane + o < 32) v += u;
        }
        if (lane == 0) s_w[wid] = v;
        __syncthreads();
        if (t < 8) {
            unsigned x = s_w[t], y = x;
#pragma unroll
            for (int o = 1; o < 8; o <<= 1) {
                unsigned u = __shfl_down_sync(0xFFu, y, o);
                if (t + o < 8) y += u;
            }
            s_w[t] = y - x;
        }
        __syncthreads();
        unsigned above = (v - sl) + s_w[wid];
#pragma unroll
        for (int x = 15; x >= 0; x--) {
            unsigned hcur = hist[t * 16 + x];
            if (above < KTOP && above + hcur >= KTOP) {
                s_T = t * 16 + x;
                s_above = above;
            }
            above += hcur;
        }
        __syncthreads();

        // gather: flag above-threshold; collect threshold-bin candidates
        int T = s_T;
        unsigned long long* cand = reinterpret_cast<unsigned long long*>(hist);
#pragma unroll
        for (int c = 0; c < 16; c++) {
            int i = t + 256 * c;
            unsigned k = __ldcg(&g_keys[b * SS + i]);
            int bin = (int)(k >> 20);
            if (bin > T) {
                g_flag[b * SS + i] = 1;
            } else if (bin == T) {
                unsigned p = atomicAdd(&s_ncand, 1u);
                if (p < 2048)
                    cand[p] = ((unsigned long long)k << 32) |
                              (unsigned long long)(0xFFFFFFFFu - (unsigned)i);
            }
        }
        __syncthreads();
        if (t < 32) {
            int n = (int)min(s_ncand, 2048u);
            int r = KTOP - (int)s_above;
            for (int it = 0; it < r; it++) {
                unsigned long long best = 0ull;
                for (int idx = lane; idx < n; idx += 32) {
                    unsigned long long c2 = cand[idx];
                    if (c2 > best) best = c2;
                }
#pragma unroll
                for (int o = 16; o; o >>= 1) {
                    unsigned long long u = __shfl_xor_sync(0xffffffffu, best, o);
                    if (u > best) best = u;
                }
                if (lane == 0) {
                    unsigned sel = 0xFFFFFFFFu - (unsigned)(best & 0xFFFFFFFFull);
                    g_flag[b * SS + sel] = 1;
                }
                for (int idx = lane; idx < n; idx += 32)
                    if (cand[idx] == best) cand[idx] = 0ull;
                __syncwarp();
            }
        }
        __syncthreads();

        // bitmasks; materialize prefval + fvalid
        unsigned mV = 0, mF = 0;
#pragma unroll
        for (int k2 = 0; k2 < 16; k2++) {
            int j = t * 16 + k2;
            if (am[b * SS + j]) mV |= 1u << k2;
            if (__ldcg(&g_flag[b * SS + j])) mF |= 1u << k2;
        }
        unsigned mFV = mF & mV;
#pragma unroll
        for (int k2 = 0; k2 < 16; k2++) {
            int j = t * 16 + k2;
            g_prefval[b * SS + j] = ((mFV >> k2) & 1) ? 1.f : 0.f;
            g_fvalid[b * SS + j] = ((mV >> k2) & 1) ? 1.f : 0.f;
        }

        // packed inclusive prefix (low16=valid, high16=flag&valid) into hist
        unsigned* P = hist;
        unsigned tot = 0;
#pragma unroll
        for (int k2 = 0; k2 < 16; k2++)
            tot += ((mV >> k2) & 1) + ((((mFV >> k2) & 1)) << 16);
        unsigned pv2 = tot;
#pragma unroll
        for (int o = 1; o < 32; o <<= 1) {
            unsigned u = __shfl_up_sync(0xffffffffu, pv2, o);
            if (lane >= o) pv2 += u;
        }
        if (lane == 31) s_w2[wid] = pv2;
        __syncthreads();
        if (t < 8) {
            unsigned x = s_w2[t], y = x;
#pragma unroll
            for (int o = 1; o < 8; o <<= 1) {
                unsigned u = __shfl_up_sync(0xFFu, y, o);
                if (t >= o) y += u;
            }
            s_w2[t] = y - x;
        }
        __syncthreads();
        unsigned run = s_w2[wid] + (pv2 - tot);
#pragma unroll
        for (int k2 = 0; k2 < 16; k2++) {
            run += ((mV >> k2) & 1) + ((((mFV >> k2) & 1)) << 16);
            P[t * 16 + k2] = run;
        }
        __syncthreads();

        // analytic per-row counts
        unsigned total = 0;
#pragma unroll
        for (int k2 = 0; k2 < 16; k2++) {
            int i = t * 16 + k2;
            if ((mV >> k2) & 1) {
                int lim0 = i - (WND - 1);
                if (lim0 < 0) lim0 = 0;
                unsigned Pi = P[i];
                unsigned Plim = lim0 ? P[lim0 - 1] : 0u;
                unsigned nvw = (Pi & 0xFFFFu) - (Plim & 0xFFFFu);
                total += nvw + (((mF >> k2) & 1) ? (Plim & 0xFFFFu) : (Plim >> 16));
            }
        }
#pragma unroll
        for (int o = 16; o; o >>= 1) total += __shfl_xor_sync(0xffffffffu, total, o);
        if (lane == 0) s_w2[wid] = total;
        __syncthreads();

        // selected (all true for W>=1) + efficiency
        long long basep = (long long)BB * SS * SS;
        for (int c = 0; c < 4; c++) {
            long long p0 = basep + (long long)b * SS + 4 * (t + c * 256);
            if (p0 + 3 < out_size) {
                *reinterpret_cast<float4*>(out + p0) = make_float4(1.f, 1.f, 1.f, 1.f);
            } else {
                for (int k2 = 0; k2 < 4; k2++)
                    if (p0 + k2 < out_size) out[p0 + k2] = 1.f;
            }
        }
        if (t == 0) {
            unsigned stot = 0;
#pragma unroll
            for (int x = 0; x < 8; x++) stot += s_w2[x];
            long long p = basep + (long long)BB * SS + b;
            if (p < out_size) out[p] = (float)stot / ((float)SS * (float)SS);
            __threadfence();
            atomicExch(&g_ready[b], 1u);
        }
        return;
    }

    // ============ role 3: regionA rows — window + zeros (am only) ===========
    if (bid < NSC + BB + NJA) {
        int idx = bid - (NSC + BB);
        int b = idx >> 12;
        int i = idx & (SS - 1);
        int validi = am[b * SS + i];
        int lim0 = i - (WND - 1);
        if (lim0 < 0) lim0 = 0;
        int V = (lim0 + 3) >> 2;
        float4* orow = reinterpret_cast<float4*>(out + ((size_t)(b * SS) + i) * SS);
        const int4* amv = reinterpret_cast<const int4*>(am + b * SS);
        for (int v4 = V + t; v4 < SS / 4; v4 += 256) {
            int j0 = 4 * v4;
            float4 r;
            if (!validi || j0 > i) {
                r = make_float4(0.f, 0.f, 0.f, 0.f);
            } else {
                int4 a4 = amv[v4];
                if (j0 + 3 <= i) {
                    r.x = a4.x ? 1.f : 0.f;
                    r.y = a4.y ? 1.f : 0.f;
                    r.z = a4.z ? 1.f : 0.f;
                    r.w = a4.w ? 1.f : 0.f;
                } else {
                    r.x = (j0 <= i && a4.x) ? 1.f : 0.f;
                    r.y = (j0 + 1 <= i && a4.y) ? 1.f : 0.f;
                    r.z = (j0 + 2 <= i && a4.z) ? 1.f : 0.f;
                    r.w = (j0 + 3 <= i && a4.w) ? 1.f : 0.f;
                }
            }
            __stcs(&orow[v4], r);
        }
        return;
    }

    // ============ role 4: regionB rows — prefix [0, lim0) (needs flags) =====
    {
        int idx = bid - (NSC + BB + NJA);
        int b = idx / (SS - WND);
        int i = WND + (idx - b * (SS - WND));
        if (t == 0) {
            while (*(volatile unsigned*)&g_ready[b] == 0u) __nanosleep(64);
            __threadfence();
        }
        __syncthreads();

        int validi = am[b * SS + i];
        int rowAll = __ldcg(&g_flag[b * SS + i]);
        int lim0 = i - (WND - 1);       // >= 1
        int V = (lim0 + 3) >> 2;
        const float4* pv = reinterpret_cast<const float4*>(
            (rowAll ? g_fvalid : g_prefval) + b * SS);
        const float4* fv = reinterpret_cast<const float4*>(g_fvalid + b * SS);
        float4* orow = reinterpret_cast<float4*>(out + ((size_t)(b * SS) + i) * SS);
        for (int v4 = t; v4 < V; v4 += 256) {
            int j0 = 4 * v4;
            float4 r;
            if (!validi) {
                r = make_float4(0.f, 0.f, 0.f, 0.f);
            } else if (j0 + 3 < lim0) {
                r = pv[v4];
            } else {
                float4 p = pv[v4];
                float4 f = fv[v4];
                r.x = (j0 >= lim0) ? f.x : p.x;
                r.y = (j0 + 1 >= lim0) ? f.y : p.y;
                r.z = (j0 + 2 >= lim0) ? f.z : p.z;
                r.w = (j0 + 3 >= lim0) ? f.w : p.w;
            }
            __stcs(&orow[v4], r);
        }
    }
}

extern "C" void kernel_launch(void* const* d_in, const int* in_sizes, int n_in,
                              void* d_out, int out_size) {
    const float* h = (const float*)d_in[0];
    const int* am = (const int*)d_in[1];
    const float* w = (const float*)d_in[2];
    float* out = (float*)d_out;

    init_kernel<<<1, 32>>>();
    fused_kernel<<<GRID_TOTAL, 256>>>(h, am, w, out, (long long)out_size);
}

// round 7
// speedup vs baseline: 1.3194x; 1.3194x over previous
#include <cuda_runtime.h>
#include <math_constants.h>

#define BB 4
#define SS 4096
#define DD 1024
#define WND 128
#define KTOP 64
#define RSTRIDE 10
#define RBUDGET 409

#define NSC 2048                    /* scores jobs (1 row per warp, 8/block) */
#define NJA (BB * SS)               /* regionA rows                          */
#define NJB (BB * (SS - WND))       /* regionB rows                          */
#define INTER (3 * NSC)             /* interleaved section length (6144)     */
#define GRID1 (4 + NSC + NJA)       /* 18436                                 */

// scratch (no allocation allowed)
__device__ unsigned g_keys[BB * SS];
__device__ unsigned char g_flag[BB * SS];
__device__ float g_prefval[BB * SS];
__device__ float g_fvalid[BB * SS];
__device__ unsigned g_scoresDone;   // zeroed at static init; K2 resets it

// ===========================================================================
// K1: topk(4) | scores:regionA 1:2 interleave | regionA remainder
// ===========================================================================
__global__ void __launch_bounds__(256, 6)
k1_kernel(const float* __restrict__ h, const int* __restrict__ am,
          const float* __restrict__ w, float* __restrict__ out,
          long long out_size) {
    __shared__ unsigned hist[4096];   // used by topk blocks only
    __shared__ unsigned s_w[8];
    __shared__ unsigned s_w2[8];
    __shared__ int s_T;
    __shared__ unsigned s_above, s_ncand;

    int bid = blockIdx.x;
    int t = threadIdx.x;
    int lane = t & 31, wid = t >> 5;

    // ---------------- role assignment ----------------
    int scoreIdx = -1, rowAIdx = -1;
    if (bid >= 4) {
        int local = bid - 4;
        if (local < INTER) {
            if (local % 3 == 0) scoreIdx = local / 3;
            else rowAIdx = local - local / 3 - 1;
        } else {
            rowAIdx = (INTER - NSC) + (local - INTER);   // 4096 + ...
        }
    }

    // ===================== scores role =====================
    if (scoreIdx >= 0) {
        int r = scoreIdx * 8 + wid;   // one row per warp
        const float4* hv = reinterpret_cast<const float4*>(h + (size_t)r * DD);
        const float4* wv = reinterpret_cast<const float4*>(w);
        float acc0 = 0.f, acc1 = 0.f;
#pragma unroll
        for (int half = 0; half < 2; half++) {
            float4 a[4];
#pragma unroll
            for (int u = 0; u < 4; u++)
                a[u] = __ldcs(&hv[lane + (half * 4 + u) * 32]);
#pragma unroll
            for (int u = 0; u < 4; u++) {
                float4 bw = wv[lane + (half * 4 + u) * 32];
                acc0 += a[u].x * bw.x + a[u].y * bw.y;
                acc1 += a[u].z * bw.z + a[u].w * bw.w;
            }
        }
        float acc = acc0 + acc1;
#pragma unroll
        for (int o = 16; o; o >>= 1) acc += __shfl_xor_sync(0xffffffffu, acc, o);
        if (lane == 0) {
            int amv = am[r];
            float vv = amv ? acc : -CUDART_INF_F;
            unsigned k = __float_as_uint(vv);
            k = (k & 0x80000000u) ? ~k : (k | 0x80000000u);
            g_keys[r] = k;
            int s = r & (SS - 1);
            g_flag[r] = ((s % RSTRIDE) == 0 && (s / RSTRIDE) < RBUDGET) ? 1 : 0;
        }
        __syncthreads();
        if (t == 0) {
            __threadfence();
            atomicAdd(&g_scoresDone, 1u);
        }
        return;
    }

    // ===================== regionA role (window + zeros) ====================
    if (rowAIdx >= 0) {
        int b = rowAIdx >> 12;
        int i = rowAIdx & (SS - 1);
        int validi = am[b * SS + i];
        int lim0 = i - (WND - 1);
        if (lim0 < 0) lim0 = 0;
        int V = (lim0 + 3) >> 2;
        float4* orow = reinterpret_cast<float4*>(out + ((size_t)(b * SS) + i) * SS);
        const int4* amv = reinterpret_cast<const int4*>(am + b * SS);
        for (int v4 = V + t; v4 < SS / 4; v4 += 256) {
            int j0 = 4 * v4;
            float4 r;
            if (!validi || j0 > i) {
                r = make_float4(0.f, 0.f, 0.f, 0.f);
            } else {
                int4 a4 = amv[v4];
                if (j0 + 3 <= i) {
                    r.x = a4.x ? 1.f : 0.f;
                    r.y = a4.y ? 1.f : 0.f;
                    r.z = a4.z ? 1.f : 0.f;
                    r.w = a4.w ? 1.f : 0.f;
                } else {
                    r.x = (j0 <= i && a4.x) ? 1.f : 0.f;
                    r.y = (j0 + 1 <= i && a4.y) ? 1.f : 0.f;
                    r.z = (j0 + 2 <= i && a4.z) ? 1.f : 0.f;
                    r.w = (j0 + 3 <= i && a4.w) ? 1.f : 0.f;
                }
            }
            __stcs(&orow[v4], r);
        }
        return;
    }

    // ===================== topk role (bids 0..3) ============================
    {
        int b = bid;
        if (t == 0) {
            while (*(volatile unsigned*)&g_scoresDone < (unsigned)NSC)
                __nanosleep(128);
            __threadfence();
        }
        __syncthreads();

        // histogram of top-12 key bits
#pragma unroll
        for (int c = 0; c < 16; c++) hist[t + 256 * c] = 0;
        if (t == 0) s_ncand = 0;
        __syncthreads();
#pragma unroll
        for (int c = 0; c < 16; c++) {
            unsigned k = __ldcg(&g_keys[b * SS + t + 256 * c]);
            atomicAdd(&hist[k >> 20], 1u);
        }
        __syncthreads();

        // suffix scan: keys in bins strictly above each bin
        unsigned sl = 0;
#pragma unroll
        for (int x = 0; x < 16; x++) sl += hist[t * 16 + x];
        unsigned v = sl;
#pragma unroll
        for (int o = 1; o < 32; o <<= 1) {
            unsigned u = __shfl_down_sync(0xffffffffu, v, o);
            if (lane + o < 32) v += u;
        }
        if (lane == 0) s_w[wid] = v;
        __syncthreads();
        if (t < 8) {
            unsigned x = s_w[t], y = x;
#pragma unroll
            for (int o = 1; o < 8; o <<= 1) {
                unsigned u = __shfl_down_sync(0xFFu, y, o);
                if (t + o < 8) y += u;
            }
            s_w[t] = y - x;
        }
        __syncthreads();
        unsigned above = (v - sl) + s_w[wid];
#pragma unroll
        for (int x = 15; x >= 0; x--) {
            unsigned hcur = hist[t * 16 + x];
            if (above < KTOP && above + hcur >= KTOP) {
                s_T = t * 16 + x;
                s_above = above;
            }
            above += hcur;
        }
        __syncthreads();

        int T = s_T;
        unsigned long long* cand = reinterpret_cast<unsigned long long*>(hist);
#pragma unroll
        for (int c = 0; c < 16; c++) {
            int i = t + 256 * c;
            unsigned k = __ldcg(&g_keys[b * SS + i]);
            int bin = (int)(k >> 20);
            if (bin > T) {
                g_flag[b * SS + i] = 1;
            } else if (bin == T) {
                unsigned p = atomicAdd(&s_ncand, 1u);
                if (p < 2048)
                    cand[p] = ((unsigned long long)k << 32) |
                              (unsigned long long)(0xFFFFFFFFu - (unsigned)i);
            }
        }
        __syncthreads();
        if (t < 32) {
            int n = (int)min(s_ncand, 2048u);
            int r = KTOP - (int)s_above;
            for (int it = 0; it < r; it++) {
                unsigned long long best = 0ull;
                for (int idx = lane; idx < n; idx += 32) {
                    unsigned long long c2 = cand[idx];
                    if (c2 > best) best = c2;
                }
#pragma unroll
                for (int o = 16; o; o >>= 1) {
                    unsigned long long u = __shfl_xor_sync(0xffffffffu, best, o);
                    if (u > best) best = u;
                }
                if (lane == 0) {
                    unsigned sel = 0xFFFFFFFFu - (unsigned)(best & 0xFFFFFFFFull);
                    g_flag[b * SS + sel] = 1;
                }
                for (int idx = lane; idx < n; idx += 32)
                    if (cand[idx] == best) cand[idx] = 0ull;
                __syncwarp();
            }
        }
        __syncthreads();

        // bitmasks; materialize prefval + fvalid
        unsigned mV = 0, mF = 0;
#pragma unroll
        for (int k2 = 0; k2 < 16; k2++) {
            int j = t * 16 + k2;
            if (am[b * SS + j]) mV |= 1u << k2;
            if (__ldcg(&g_flag[b * SS + j])) mF |= 1u << k2;
        }
        unsigned mFV = mF & mV;
#pragma unroll
        for (int k2 = 0; k2 < 16; k2++) {
            int j = t * 16 + k2;
            g_prefval[b * SS + j] = ((mFV >> k2) & 1) ? 1.f : 0.f;
            g_fvalid[b * SS + j] = ((mV >> k2) & 1) ? 1.f : 0.f;
        }

        // packed inclusive prefix (low16=valid, high16=flag&valid)
        unsigned* P = hist;
        unsigned tot = 0;
#pragma unroll
        for (int k2 = 0; k2 < 16; k2++)
            tot += ((mV >> k2) & 1) + ((((mFV >> k2) & 1)) << 16);
        unsigned pv2 = tot;
#pragma unroll
        for (int o = 1; o < 32; o <<= 1) {
            unsigned u = __shfl_up_sync(0xffffffffu, pv2, o);
            if (lane >= o) pv2 += u;
        }
        if (lane == 31) s_w2[wid] = pv2;
        __syncthreads();
        if (t < 8) {
            unsigned x = s_w2[t], y = x;
#pragma unroll
            for (int o = 1; o < 8; o <<= 1) {
                unsigned u = __shfl_up_sync(0xFFu, y, o);
                if (t >= o) y += u;
            }
            s_w2[t] = y - x;
        }
        __syncthreads();
        unsigned run = s_w2[wid] + (pv2 - tot);
#pragma unroll
        for (int k2 = 0; k2 < 16; k2++) {
            run += ((mV >> k2) & 1) + ((((mFV >> k2) & 1)) << 16);
            P[t * 16 + k2] = run;
        }
        __syncthreads();

        // analytic per-row counts
        unsigned total = 0;
#pragma unroll
        for (int k2 = 0; k2 < 16; k2++) {
            int i = t * 16 + k2;
            if ((mV >> k2) & 1) {
                int lim0 = i - (WND - 1);
                if (lim0 < 0) lim0 = 0;
                unsigned Pi = P[i];
                unsigned Plim = lim0 ? P[lim0 - 1] : 0u;
                unsigned nvw = (Pi & 0xFFFFu) - (Plim & 0xFFFFu);
                total += nvw + (((mF >> k2) & 1) ? (Plim & 0xFFFFu) : (Plim >> 16));
            }
        }
#pragma unroll
        for (int o = 16; o; o >>= 1) total += __shfl_xor_sync(0xffffffffu, total, o);
        if (lane == 0) s_w2[wid] = total;
        __syncthreads();

        // selected (all true for W>=1) + efficiency
        long long basep = (long long)BB * SS * SS;
        for (int c = 0; c < 4; c++) {
            long long p0 = basep + (long long)b * SS + 4 * (t + c * 256);
            if (p0 + 3 < out_size) {
                *reinterpret_cast<float4*>(out + p0) = make_float4(1.f, 1.f, 1.f, 1.f);
            } else {
                for (int k2 = 0; k2 < 4; k2++)
                    if (p0 + k2 < out_size) out[p0 + k2] = 1.f;
            }
        }
        if (t == 0) {
            unsigned stot = 0;
#pragma unroll
            for (int x = 0; x < 8; x++) stot += s_w2[x];
            long long p = basep + (long long)BB * SS + b;
            if (p < out_size) out[p] = (float)stot / ((float)SS * (float)SS);
        }
    }
}

// ===========================================================================
// K2: regionB prefix rows [0, lim0) — flags/prefval final (kernel ordering)
// ===========================================================================
__global__ void __launch_bounds__(256)
k2_kernel(const int* __restrict__ am, float* __restrict__ out) {
    int idx = blockIdx.x;
    int t = threadIdx.x;
    if (idx == 0 && t == 0) g_scoresDone = 0u;   // reset for next graph replay

    int b = idx / (SS - WND);
    int i = WND + (idx - b * (SS - WND));
    int validi = am[b * SS + i];
    int rowAll = g_flag[b * SS + i];
    int lim0 = i - (WND - 1);       // >= 1
    int V = (lim0 + 3) >> 2;
    const float4* pv = reinterpret_cast<const float4*>(
        (rowAll ? g_fvalid : g_prefval) + b * SS);
    const float4* fv = reinterpret_cast<const float4*>(g_fvalid + b * SS);
    float4* orow = reinterpret_cast<float4*>(out + ((size_t)(b * SS) + i) * SS);
    for (int v4 = t; v4 < V; v4 += 256) {
        int j0 = 4 * v4;
        float4 r;
        if (!validi) {
            r = make_float4(0.f, 0.f, 0.f, 0.f);
        } else if (j0 + 3 < lim0) {
            r = pv[v4];
        } else {
            float4 p = pv[v4];
            float4 f = fv[v4];
            r.x = (j0 >= lim0) ? f.x : p.x;
            r.y = (j0 + 1 >= lim0) ? f.y : p.y;
            r.z = (j0 + 2 >= lim0) ? f.z : p.z;
            r.w = (j0 + 3 >= lim0) ? f.w : p.w;
        }
        __stcs(&orow[v4], r);
    }
}

extern "C" void kernel_launch(void* const* d_in, const int* in_sizes, int n_in,
                              void* d_out, int out_size) {
    const float* h = (const float*)d_in[0];
    const int* am = (const int*)d_in[1];
    const float* w = (const float*)d_in[2];
    float* out = (float*)d_out;

    k1_kernel<<<GRID1, 256>>>(h, am, w, out, (long long)out_size);
    k2_kernel<<<NJB, 256>>>(am, out);
}